// round 14
// baseline (speedup 1.0000x reference)
#include <cuda_runtime.h>
#include <cuda_fp16.h>
#include <cstdint>
#include <stdint.h>
#include <math.h>

#define B_    256
#define S_    300
#define NTOK  (B_*S_)        // 76800

// ---------------- scratch (__device__ globals) ------------------------------
__device__ __align__(16) __half g_q [((size_t)NTOK+16)*64];
__device__ __align__(16) __half g_k [((size_t)NTOK+16)*64];
__device__ __align__(16) __half g_v [((size_t)NTOK+16)*64];
__device__ __align__(16) float  g_z1[(size_t)NTOK*64];

// fragment-order fp16 weight streams: [ntile][lane][kstep][{b0,b1}] (half2 units)
__device__ __align__(16) __half2 g_WEf[24*32*4*2];    // 192 cols, K=64
__device__ __align__(16) __half2 g_WHf[24*32*16*2];   // 192 cols, K=256
__device__ __align__(16) __half2 g_W1f[32*32*4*2];    // 256 cols, K=64
__device__ __align__(16) __half2 g_W2f[ 8*32*16*2];   // 64 cols,  K=256

__device__ float g_bE[192], g_gE[192], g_betaE[192];
__device__ float g_bH[192], g_gH[192], g_betaH[192];

// ---------------- mma / ldmatrix helpers ------------------------------------
__device__ __forceinline__ void mma_f16(float* d, const unsigned int* a,
                                        unsigned int b0, unsigned int b1) {
    asm volatile(
        "mma.sync.aligned.m16n8k16.row.col.f32.f16.f16.f32 "
        "{%0,%1,%2,%3}, {%4,%5,%6,%7}, {%8,%9}, {%0,%1,%2,%3};\n"
        : "+f"(d[0]), "+f"(d[1]), "+f"(d[2]), "+f"(d[3])
        : "r"(a[0]), "r"(a[1]), "r"(a[2]), "r"(a[3]), "r"(b0), "r"(b1));
}
__device__ __forceinline__ void ldsm4(unsigned int* a, const void* p) {
    unsigned int s = (unsigned int)__cvta_generic_to_shared(p);
    asm volatile("ldmatrix.sync.aligned.m8n8.x4.shared.b16 {%0,%1,%2,%3}, [%4];\n"
        : "=r"(a[0]), "=r"(a[1]), "=r"(a[2]), "=r"(a[3]) : "r"(s));
}
__device__ __forceinline__ void ldsm4t(unsigned int* a, const void* p) {
    unsigned int s = (unsigned int)__cvta_generic_to_shared(p);
    asm volatile("ldmatrix.sync.aligned.m8n8.x4.trans.shared.b16 {%0,%1,%2,%3}, [%4];\n"
        : "=r"(a[0]), "=r"(a[1]), "=r"(a[2]), "=r"(a[3]) : "r"(s));
}
__device__ __forceinline__ unsigned int h2u(__half2 h) {
    return *(unsigned int*)&h;
}
// shifted softmax exp: exact (uniform shift cancels in p/l); clamp prevents
// fp16 inf (max p = e^10 = 22026 < 65504).
__device__ __forceinline__ float sexp(float s) {
    return __expf(fminf(s, 18.0f) - 8.0f);
}

// ---------------- K0: pack weights into fragment streams --------------------
__global__ void pack_kernel(
    const float* __restrict__ Wq,  const float* __restrict__ bq,
    const float* __restrict__ Wk,  const float* __restrict__ bk,
    const float* __restrict__ Wv,  const float* __restrict__ bv,
    const float* __restrict__ Wcq, const float* __restrict__ bcq,
    const float* __restrict__ Wck, const float* __restrict__ bck,
    const float* __restrict__ Wcv, const float* __restrict__ bcv,
    const float* __restrict__ gQE, const float* __restrict__ betaQE,
    const float* __restrict__ gKE, const float* __restrict__ betaKE,
    const float* __restrict__ gVE, const float* __restrict__ betaVE,
    const float* __restrict__ gQH, const float* __restrict__ betaQH,
    const float* __restrict__ gKH, const float* __restrict__ betaKH,
    const float* __restrict__ gVH, const float* __restrict__ betaVH,
    const float* __restrict__ W1,  const float* __restrict__ W2)
{
    const int tid0 = blockIdx.x * blockDim.x + threadIdx.x;
    const int stride = gridDim.x * blockDim.x;

    for (int idx = tid0; idx < 24*32*4*2; idx += stride) {
        int j = idx & 1, ks = (idx >> 1) & 3, l = (idx >> 3) & 31, nt = idx >> 8;
        int g = l >> 2, t = l & 3;
        int c = nt*8 + g;
        int k = ks*16 + 2*t + j*8;
        int br = c >> 6, cc = c & 63;
        const float* W = (br == 0) ? Wq : (br == 1) ? Wk : Wv;
        g_WEf[idx] = __floats2half2_rn(W[k*64 + cc], W[(k+1)*64 + cc]);
    }
    for (int idx = tid0; idx < 24*32*16*2; idx += stride) {
        int j = idx & 1, ks = (idx >> 1) & 15, l = (idx >> 5) & 31, nt = idx >> 10;
        int g = l >> 2, t = l & 3;
        int c = nt*8 + g;
        int k = ks*16 + 2*t + j*8;
        int br = c >> 6, cc = c & 63;
        const float* W = (br == 0) ? Wcq : (br == 1) ? Wck : Wcv;
        g_WHf[idx] = __floats2half2_rn(W[k*64 + cc], W[(k+1)*64 + cc]);
    }
    for (int idx = tid0; idx < 32*32*4*2; idx += stride) {
        int j = idx & 1, ks = (idx >> 1) & 3, l = (idx >> 3) & 31, nt = idx >> 8;
        int g = l >> 2, t = l & 3;
        int c = nt*8 + g;
        int k = ks*16 + 2*t + j*8;
        g_W1f[idx] = __floats2half2_rn(W1[k*256 + c], W1[(k+1)*256 + c]);
    }
    for (int idx = tid0; idx < 8*32*16*2; idx += stride) {
        int j = idx & 1, ks = (idx >> 1) & 15, l = (idx >> 5) & 31, nt = idx >> 10;
        int g = l >> 2, t = l & 3;
        int c = nt*8 + g;
        int k = ks*16 + 2*t + j*8;
        g_W2f[idx] = __floats2half2_rn(W2[k*64 + c], W2[(k+1)*64 + c]);
    }
    for (int c = tid0; c < 192; c += stride) {
        int br = c >> 6, j = c & 63;
        g_bE[c]    = ((br==0)?bq    :(br==1)?bk    :bv    )[j];
        g_bH[c]    = ((br==0)?bcq   :(br==1)?bck   :bcv   )[j];
        g_gE[c]    = ((br==0)?gQE   :(br==1)?gKE   :gVE   )[j];
        g_betaE[c] = ((br==0)?betaQE:(br==1)?betaKE:betaVE)[j];
        g_gH[c]    = ((br==0)?gQH   :(br==1)?gKH   :gVH   )[j];
        g_betaH[c] = ((br==0)?betaQH:(br==1)?betaKH:betaVH)[j];
    }
}

// ---------------- K1: gated projections via mma (32 tok/block, reg LN) ------
#define XR 72
#define HR 264
__global__ __launch_bounds__(256)
void proj_kernel(const float* __restrict__ state, const float* __restrict__ Hin)
{
    __shared__ __align__(16) __half Xs[32*XR];        // 4.5 KB
    __shared__ __align__(16) __half Hs[32*HR];        // 16.5 KB
    __shared__ float sP[2][32][24][2];                // 12 KB
    __shared__ float sStat[2][32][3][2];              // 1.5 KB
    const int tid = threadIdx.x;
    const size_t tok0 = (size_t)blockIdx.x * 32;

    #pragma unroll
    for (int it = 0; it < 2; it++) {
        int idx = (tid + 256*it) * 4;
        int r = idx >> 6, c = idx & 63;
        float4 f = *(const float4*)(state + (tok0 + r)*64 + c);
        *(__half2*)(Xs + r*XR + c)     = __floats2half2_rn(f.x, f.y);
        *(__half2*)(Xs + r*XR + c + 2) = __floats2half2_rn(f.z, f.w);
    }
    #pragma unroll
    for (int it = 0; it < 8; it++) {
        int idx = (tid + 256*it) * 4;
        int rh = idx >> 8, ch = idx & 255;
        float4 fh = *(const float4*)(Hin + (tok0 + rh)*256 + ch);
        *(__half2*)(Hs + rh*HR + ch)     = __floats2half2_rn(fh.x, fh.y);
        *(__half2*)(Hs + rh*HR + ch + 2) = __floats2half2_rn(fh.z, fh.w);
    }
    __syncthreads();

    const int w = tid >> 5, l = tid & 31;
    const int g = l >> 2, t = l & 3;
    const int ldrow = (l & 15), ldcol = (l >> 4) * 8;

    float accE[2][3][4];
    #pragma unroll
    for (int mt = 0; mt < 2; mt++)
        #pragma unroll
        for (int nt = 0; nt < 3; nt++)
            #pragma unroll
            for (int i = 0; i < 4; i++) accE[mt][nt][i] = 0.f;
    #pragma unroll
    for (int ksp = 0; ksp < 2; ksp++) {
        unsigned int a0[8], a1[8];
        ldsm4(a0,     Xs + ldrow*XR + ksp*32 + ldcol);
        ldsm4(a0 + 4, Xs + ldrow*XR + ksp*32 + 16 + ldcol);
        ldsm4(a1,     Xs + (16 + ldrow)*XR + ksp*32 + ldcol);
        ldsm4(a1 + 4, Xs + (16 + ldrow)*XR + ksp*32 + 16 + ldcol);
        #pragma unroll
        for (int nt = 0; nt < 3; nt++) {
            const uint4 bfrag = *(const uint4*)&g_WEf[(((w*3 + nt)*32 + l)*4 + ksp*2)*2];
            mma_f16(accE[0][nt], a0,     bfrag.x, bfrag.y);
            mma_f16(accE[0][nt], a0 + 4, bfrag.z, bfrag.w);
            mma_f16(accE[1][nt], a1,     bfrag.x, bfrag.y);
            mma_f16(accE[1][nt], a1 + 4, bfrag.z, bfrag.w);
        }
    }

    float accH[2][3][4];
    #pragma unroll
    for (int mt = 0; mt < 2; mt++)
        #pragma unroll
        for (int nt = 0; nt < 3; nt++)
            #pragma unroll
            for (int i = 0; i < 4; i++) accH[mt][nt][i] = 0.f;
    #pragma unroll
    for (int ksp = 0; ksp < 8; ksp++) {
        unsigned int a0[8], a1[8];
        ldsm4(a0,     Hs + ldrow*HR + ksp*32 + ldcol);
        ldsm4(a0 + 4, Hs + ldrow*HR + ksp*32 + 16 + ldcol);
        ldsm4(a1,     Hs + (16 + ldrow)*HR + ksp*32 + ldcol);
        ldsm4(a1 + 4, Hs + (16 + ldrow)*HR + ksp*32 + 16 + ldcol);
        #pragma unroll
        for (int nt = 0; nt < 3; nt++) {
            const uint4 bfrag = *(const uint4*)&g_WHf[(((w*3 + nt)*32 + l)*16 + ksp*2)*2];
            mma_f16(accH[0][nt], a0,     bfrag.x, bfrag.y);
            mma_f16(accH[0][nt], a0 + 4, bfrag.z, bfrag.w);
            mma_f16(accH[1][nt], a1,     bfrag.x, bfrag.y);
            mma_f16(accH[1][nt], a1 + 4, bfrag.z, bfrag.w);
        }
    }

    #pragma unroll
    for (int nt = 0; nt < 3; nt++) {
        int c0 = w*24 + nt*8 + 2*t;
        float be0 = g_bE[c0], be1 = g_bE[c0 + 1];
        float bh0 = g_bH[c0], bh1 = g_bH[c0 + 1];
        #pragma unroll
        for (int mt = 0; mt < 2; mt++) {
            accE[mt][nt][0] += be0; accE[mt][nt][1] += be1;
            accE[mt][nt][2] += be0; accE[mt][nt][3] += be1;
            accH[mt][nt][0] += bh0; accH[mt][nt][1] += bh1;
            accH[mt][nt][2] += bh0; accH[mt][nt][3] += bh1;
        }
    }

    #pragma unroll
    for (int mt = 0; mt < 2; mt++) {
        #pragma unroll
        for (int nt = 0; nt < 3; nt++) {
            int tile = w*3 + nt;
            float e1a = accE[mt][nt][0] + accE[mt][nt][1];
            float e2a = fmaf(accE[mt][nt][0], accE[mt][nt][0], accE[mt][nt][1]*accE[mt][nt][1]);
            float e1b = accE[mt][nt][2] + accE[mt][nt][3];
            float e2b = fmaf(accE[mt][nt][2], accE[mt][nt][2], accE[mt][nt][3]*accE[mt][nt][3]);
            float h1a = accH[mt][nt][0] + accH[mt][nt][1];
            float h2a = fmaf(accH[mt][nt][0], accH[mt][nt][0], accH[mt][nt][1]*accH[mt][nt][1]);
            float h1b = accH[mt][nt][2] + accH[mt][nt][3];
            float h2b = fmaf(accH[mt][nt][2], accH[mt][nt][2], accH[mt][nt][3]*accH[mt][nt][3]);
            #pragma unroll
            for (int off = 1; off <= 2; off <<= 1) {
                e1a += __shfl_xor_sync(0xffffffffu, e1a, off);
                e2a += __shfl_xor_sync(0xffffffffu, e2a, off);
                e1b += __shfl_xor_sync(0xffffffffu, e1b, off);
                e2b += __shfl_xor_sync(0xffffffffu, e2b, off);
                h1a += __shfl_xor_sync(0xffffffffu, h1a, off);
                h2a += __shfl_xor_sync(0xffffffffu, h2a, off);
                h1b += __shfl_xor_sync(0xffffffffu, h1b, off);
                h2b += __shfl_xor_sync(0xffffffffu, h2b, off);
            }
            if (t == 0) {
                int r0 = mt*16 + g, r1 = r0 + 8;
                sP[0][r0][tile][0] = e1a; sP[0][r0][tile][1] = e2a;
                sP[0][r1][tile][0] = e1b; sP[0][r1][tile][1] = e2b;
                sP[1][r0][tile][0] = h1a; sP[1][r0][tile][1] = h2a;
                sP[1][r1][tile][0] = h1b; sP[1][r1][tile][1] = h2b;
            }
        }
    }
    __syncthreads();

    if (tid < 192) {
        int eh = tid / 96, rem = tid % 96;
        int row = rem / 3, br = rem % 3;
        float s1 = 0.f, s2 = 0.f;
        #pragma unroll
        for (int tt = 0; tt < 8; tt++) {
            s1 += sP[eh][row][br*8 + tt][0];
            s2 += sP[eh][row][br*8 + tt][1];
        }
        float m = s1 * (1.f/64.f);
        float r = rsqrtf(s2*(1.f/64.f) - m*m + 1e-5f);
        sStat[eh][row][br][0] = m;
        sStat[eh][row][br][1] = r;
    }
    __syncthreads();

    #pragma unroll
    for (int nt = 0; nt < 3; nt++) {
        int tile = w*3 + nt;
        int br = tile >> 3;
        int c0 = w*24 + nt*8 + 2*t;
        float gE0 = g_gE[c0],    gE1 = g_gE[c0+1];
        float tE0 = g_betaE[c0], tE1 = g_betaE[c0+1];
        float gH0 = g_gH[c0],    gH1 = g_gH[c0+1];
        float tH0 = g_betaH[c0], tH1 = g_betaH[c0+1];
        __half* dst = (br == 0) ? g_q : (br == 1) ? g_k : g_v;
        int fc = c0 - br*64;
        #pragma unroll
        for (int mt = 0; mt < 2; mt++) {
            #pragma unroll
            for (int rh = 0; rh < 2; rh++) {
                int row = mt*16 + g + rh*8;
                float mE = sStat[0][row][br][0], rE = sStat[0][row][br][1];
                float mH = sStat[1][row][br][0], rH = sStat[1][row][br][1];
                float e0 = (accE[mt][nt][rh*2]     - mE)*rE*gE0 + tE0;
                float e1 = (accE[mt][nt][rh*2 + 1] - mE)*rE*gE1 + tE1;
                float h0 = (accH[mt][nt][rh*2]     - mH)*rH*gH0 + tH0;
                float h1 = (accH[mt][nt][rh*2 + 1] - mH)*rH*gH1 + tH1;
                *(__half2*)&dst[(tok0 + row)*64 + fc] = __floats2half2_rn(e0*h0, e1*h1);
            }
        }
    }
}

// ---------------- K2: flash attention via mma + residual -> Z1 --------------
#define KR 40
__global__ __launch_bounds__(320, 2)
void attn_kernel(const float* __restrict__ state)
{
    __shared__ __align__(16) __half Ks[304*KR];
    __shared__ __align__(16) __half Vs[304*KR];
    const int tid = threadIdx.x;
    const int b = blockIdx.x >> 1, h = blockIdx.x & 1;
    const size_t bTok = (size_t)b * S_;
    const int hoff = h * 32;

    for (int idx = tid; idx < 304*8; idx += 320) {
        int row = idx >> 3, seg = idx & 7;
        uint2 kv = make_uint2(0u, 0u), vv = make_uint2(0u, 0u);
        if (row < S_) {
            kv = *(const uint2*)&g_k[(bTok + row)*64 + hoff + seg*4];
            vv = *(const uint2*)&g_v[(bTok + row)*64 + hoff + seg*4];
        }
        *(uint2*)&Ks[row*KR + seg*4] = kv;
        *(uint2*)&Vs[row*KR + seg*4] = vv;
    }
    __syncthreads();

    const int w = tid >> 5, l = tid & 31;
    const int g = l >> 2, t = l & 3;
    const int qt0 = (2*w   < 19) ? 2*w   : 18;
    const int qt1 = (2*w+1 < 19) ? 2*w+1 : 18;
    const int q0a = qt0*16, q0b = qt1*16;

    unsigned int aq[2][2][4];
    #pragma unroll
    for (int qi = 0; qi < 2; qi++) {
        int q0 = qi ? q0b : q0a;
        #pragma unroll
        for (int ks = 0; ks < 2; ks++) {
            const __half* r0p = g_q + (bTok + q0 + g    )*64 + hoff + ks*16 + 2*t;
            const __half* r1p = g_q + (bTok + q0 + g + 8)*64 + hoff + ks*16 + 2*t;
            aq[qi][ks][0] = *(const unsigned int*)r0p;
            aq[qi][ks][1] = *(const unsigned int*)r1p;
            aq[qi][ks][2] = *(const unsigned int*)(r0p + 8);
            aq[qi][ks][3] = *(const unsigned int*)(r1p + 8);
        }
    }

    float out[2][4][4];
    float lsum[2][2];
    #pragma unroll
    for (int qi = 0; qi < 2; qi++) {
        lsum[qi][0] = 0.f; lsum[qi][1] = 0.f;
        #pragma unroll
        for (int nt = 0; nt < 4; nt++)
            #pragma unroll
            for (int i = 0; i < 4; i++) out[qi][nt][i] = 0.f;
    }

    const float SC = 0.17677669529663687f;   // 1/sqrt(32)

    for (int kc = 0; kc < 19; kc++) {
        unsigned int kb0[4], kb1[4];
        ldsm4(kb0, Ks + (kc*16 +     (l & 7))*KR + (l >> 3)*8);
        ldsm4(kb1, Ks + (kc*16 + 8 + (l & 7))*KR + (l >> 3)*8);
        unsigned int vb[8];
        ldsm4t(vb,     Vs + (kc*16 + ((l >> 3) & 1)*8 + (l & 7))*KR + (l >> 4)*8);
        ldsm4t(vb + 4, Vs + (kc*16 + ((l >> 3) & 1)*8 + (l & 7))*KR + 16 + (l >> 4)*8);

        #pragma unroll
        for (int qi = 0; qi < 2; qi++) {
            float sc0[4] = {0.f,0.f,0.f,0.f};
            float sc1[4] = {0.f,0.f,0.f,0.f};
            mma_f16(sc0, aq[qi][0], kb0[0], kb0[1]);
            mma_f16(sc0, aq[qi][1], kb0[2], kb0[3]);
            mma_f16(sc1, aq[qi][0], kb1[0], kb1[1]);
            mma_f16(sc1, aq[qi][1], kb1[2], kb1[3]);

            float p00 = sexp(sc0[0]*SC), p01 = sexp(sc0[1]*SC);
            float p02 = sexp(sc0[2]*SC), p03 = sexp(sc0[3]*SC);
            float p10 = sexp(sc1[0]*SC), p11 = sexp(sc1[1]*SC);
            float p12 = sexp(sc1[2]*SC), p13 = sexp(sc1[3]*SC);
            if (kc == 18 && t >= 2) {
                p10 = 0.f; p11 = 0.f; p12 = 0.f; p13 = 0.f;
            }
            lsum[qi][0] += (p00 + p01) + (p10 + p11);
            lsum[qi][1] += (p02 + p03) + (p12 + p13);

            unsigned int pf[4];
            pf[0] = h2u(__floats2half2_rn(p00, p01));
            pf[1] = h2u(__floats2half2_rn(p02, p03));
            pf[2] = h2u(__floats2half2_rn(p10, p11));
            pf[3] = h2u(__floats2half2_rn(p12, p13));

            mma_f16(out[qi][0], pf, vb[0], vb[1]);
            mma_f16(out[qi][1], pf, vb[2], vb[3]);
            mma_f16(out[qi][2], pf, vb[4], vb[5]);
            mma_f16(out[qi][3], pf, vb[6], vb[7]);
        }
    }

    #pragma unroll
    for (int qi = 0; qi < 2; qi++) {
        int q0 = qi ? q0b : q0a;
        float l0 = lsum[qi][0], l1 = lsum[qi][1];
        l0 += __shfl_xor_sync(0xffffffffu, l0, 1);
        l0 += __shfl_xor_sync(0xffffffffu, l0, 2);
        l1 += __shfl_xor_sync(0xffffffffu, l1, 1);
        l1 += __shfl_xor_sync(0xffffffffu, l1, 2);
        float inv0 = 1.f / l0, inv1 = 1.f / l1;
        size_t r0 = bTok + q0 + g;
        size_t r1 = r0 + 8;
        bool wr1 = (q0 + g + 8) < S_;
        #pragma unroll
        for (int nt = 0; nt < 4; nt++) {
            int c = hoff + nt*8 + 2*t;
            float2 s0 = *(const float2*)&state[r0*64 + c];
            float2 o0;
            o0.x = fmaf(out[qi][nt][0], inv0, s0.x);
            o0.y = fmaf(out[qi][nt][1], inv0, s0.y);
            *(float2*)&g_z1[r0*64 + c] = o0;
            if (wr1) {
                float2 s1 = *(const float2*)&state[r1*64 + c];
                float2 o1;
                o1.x = fmaf(out[qi][nt][2], inv1, s1.x);
                o1.y = fmaf(out[qi][nt][3], inv1, s1.y);
                *(float2*)&g_z1[r1*64 + c] = o1;
            }
        }
    }
}

// ---------------- K3: LN -> FFN(gelu) -> +Z1 via mma (64 tok/block) ---------
// 64 tokens/block (4 m16 tiles), 256 threads (8 warps).
// GEMM1: warp w owns cols w*32..w*32+31 for ALL 4 m-tiles (B-frag reuse 4x).
// GEMM2: warp = (mt = w&3, np = w>>2) covering 32 cols.
// No Z1 stash: epilogue re-reads g_z1 (L2-resident).
#define ZR  72
#define H3R 264
__global__ __launch_bounds__(256)
void ffn_kernel(const float* __restrict__ b1, const float* __restrict__ b2,
                const float* __restrict__ g1, const float* __restrict__ beta1,
                float* __restrict__ out)
{
    __shared__ __align__(16) __half Z2s[64*ZR];       // 9.2 KB
    __shared__ __align__(16) __half H3s[64*H3R];      // 33.8 KB
    const int tid = threadIdx.x;
    const size_t tok0 = (size_t)blockIdx.x * 64;

    // ---- Phase 1: LN(z1) -> fp16. 4 threads/token, 16 cols each. ----
    {
        int tk = tid >> 2, sg = tid & 3;
        const float* src = g_z1 + (tok0 + tk)*64 + sg*16;
        float4 f0 = *(const float4*)src;
        float4 f1 = *(const float4*)(src + 4);
        float4 f2 = *(const float4*)(src + 8);
        float4 f3 = *(const float4*)(src + 12);
        float v[16] = {f0.x, f0.y, f0.z, f0.w, f1.x, f1.y, f1.z, f1.w,
                       f2.x, f2.y, f2.z, f2.w, f3.x, f3.y, f3.z, f3.w};
        float s1 = 0.f, s2 = 0.f;
        #pragma unroll
        for (int u = 0; u < 16; u++) { s1 += v[u]; s2 = fmaf(v[u], v[u], s2); }
        #pragma unroll
        for (int off = 1; off <= 2; off <<= 1) {
            s1 += __shfl_xor_sync(0xffffffffu, s1, off);
            s2 += __shfl_xor_sync(0xffffffffu, s2, off);
        }
        float m = s1 * (1.f/64.f);
        float r = rsqrtf(s2*(1.f/64.f) - m*m + 1e-5f);
        #pragma unroll
        for (int u = 0; u < 16; u += 2) {
            int c = sg*16 + u;
            float a0 = (v[u]   - m)*r*g1[c]   + beta1[c];
            float a1 = (v[u+1] - m)*r*g1[c+1] + beta1[c+1];
            *(__half2*)(Z2s + tk*ZR + c) = __floats2half2_rn(a0, a1);
        }
    }
    __syncthreads();

    const int w = tid >> 5, l = tid & 31;
    const int g = l >> 2, t = l & 3;
    const int ldrow = (l & 15), ldcol = (l >> 4) * 8;

    // ---- GEMM1: [64,64]@W1 -> [64,256], exact GELU ----
    // Warp w: cols w*32 + nt*8, nt=0..3; all 4 m-tiles.
    {
        float acc1[4][4][4];
        #pragma unroll
        for (int mt = 0; mt < 4; mt++)
            #pragma unroll
            for (int nt = 0; nt < 4; nt++)
                #pragma unroll
                for (int i = 0; i < 4; i++) acc1[mt][nt][i] = 0.f;
        #pragma unroll
        for (int ksp = 0; ksp < 2; ksp++) {
            unsigned int a[4][8];
            #pragma unroll
            for (int mt = 0; mt < 4; mt++) {
                ldsm4(a[mt],     Z2s + (mt*16 + ldrow)*ZR + ksp*32 + ldcol);
                ldsm4(a[mt] + 4, Z2s + (mt*16 + ldrow)*ZR + ksp*32 + 16 + ldcol);
            }
            #pragma unroll
            for (int nt = 0; nt < 4; nt++) {
                const uint4 bfrag = *(const uint4*)&g_W1f[(((w*4 + nt)*32 + l)*4 + ksp*2)*2];
                #pragma unroll
                for (int mt = 0; mt < 4; mt++) {
                    mma_f16(acc1[mt][nt], a[mt],     bfrag.x, bfrag.y);
                    mma_f16(acc1[mt][nt], a[mt] + 4, bfrag.z, bfrag.w);
                }
            }
        }
        #pragma unroll
        for (int nt = 0; nt < 4; nt++) {
            int c0 = w*32 + nt*8 + 2*t;
            float bb0 = b1[c0], bb1 = b1[c0 + 1];
            #pragma unroll
            for (int mt = 0; mt < 4; mt++) {
                float x0 = acc1[mt][nt][0] + bb0, x1 = acc1[mt][nt][1] + bb1;
                float x2 = acc1[mt][nt][2] + bb0, x3 = acc1[mt][nt][3] + bb1;
                x0 = 0.5f*x0*(1.f + erff(x0*0.70710678118654752f));
                x1 = 0.5f*x1*(1.f + erff(x1*0.70710678118654752f));
                x2 = 0.5f*x2*(1.f + erff(x2*0.70710678118654752f));
                x3 = 0.5f*x3*(1.f + erff(x3*0.70710678118654752f));
                *(__half2*)(H3s + (mt*16 + g)*H3R + c0)     = __floats2half2_rn(x0, x1);
                *(__half2*)(H3s + (mt*16 + g + 8)*H3R + c0) = __floats2half2_rn(x2, x3);
            }
        }
    }
    __syncthreads();

    // ---- GEMM2: [64,256]@W2 -> [64,64], + b2 + residual (from g_z1) ----
    {
        const int mt = w & 3, np = w >> 2;
        float acc2[4][4];
        #pragma unroll
        for (int nt = 0; nt < 4; nt++)
            #pragma unroll
            for (int i = 0; i < 4; i++) acc2[nt][i] = 0.f;
        #pragma unroll
        for (int ksp = 0; ksp < 8; ksp++) {
            unsigned int a[8];
            ldsm4(a,     H3s + (mt*16 + ldrow)*H3R + ksp*32 + ldcol);
            ldsm4(a + 4, H3s + (mt*16 + ldrow)*H3R + ksp*32 + 16 + ldcol);
            #pragma unroll
            for (int nt = 0; nt < 4; nt++) {
                const uint4 bfrag = *(const uint4*)&g_W2f[(((np*4 + nt)*32 + l)*16 + ksp*2)*2];
                mma_f16(acc2[nt], a,     bfrag.x, bfrag.y);
                mma_f16(acc2[nt], a + 4, bfrag.z, bfrag.w);
            }
        }
        #pragma unroll
        for (int nt = 0; nt < 4; nt++) {
            int c0 = np*32 + nt*8 + 2*t;
            int r0 = mt*16 + g;
            float bb0 = b2[c0], bb1 = b2[c0 + 1];
            float2 z0 = *(const float2*)&g_z1[(tok0 + r0)*64 + c0];
            float2 z1v = *(const float2*)&g_z1[(tok0 + r0 + 8)*64 + c0];
            out[(tok0 + r0)*64 + c0]       = acc2[nt][0] + bb0 + z0.x;
            out[(tok0 + r0)*64 + c0 + 1]   = acc2[nt][1] + bb1 + z0.y;
            out[(tok0 + r0 + 8)*64 + c0]   = acc2[nt][2] + bb0 + z1v.x;
            out[(tok0 + r0 + 8)*64 + c0+1] = acc2[nt][3] + bb1 + z1v.y;
        }
    }
}

// ---------------- launcher --------------------------------------------------
extern "C" void kernel_launch(void* const* d_in, const int* in_sizes, int n_in,
                              void* d_out, int out_size)
{
    const float* state  = (const float*)d_in[0];
    const float* H      = (const float*)d_in[1];
    const float* Wq     = (const float*)d_in[2];
    const float* bq     = (const float*)d_in[3];
    const float* Wk     = (const float*)d_in[4];
    const float* bk     = (const float*)d_in[5];
    const float* Wv     = (const float*)d_in[6];
    const float* bv     = (const float*)d_in[7];
    const float* Wcq    = (const float*)d_in[8];
    const float* bcq    = (const float*)d_in[9];
    const float* Wck    = (const float*)d_in[10];
    const float* bck    = (const float*)d_in[11];
    const float* Wcv    = (const float*)d_in[12];
    const float* bcv    = (const float*)d_in[13];
    const float* gQE    = (const float*)d_in[14];
    const float* betaQE = (const float*)d_in[15];
    const float* gKE    = (const float*)d_in[16];
    const float* betaKE = (const float*)d_in[17];
    const float* gVE    = (const float*)d_in[18];
    const float* betaVE = (const float*)d_in[19];
    const float* gQH    = (const float*)d_in[20];
    const float* betaQH = (const float*)d_in[21];
    const float* gKH    = (const float*)d_in[22];
    const float* betaKH = (const float*)d_in[23];
    const float* gVH    = (const float*)d_in[24];
    const float* betaVH = (const float*)d_in[25];
    const float* W1     = (const float*)d_in[26];
    const float* b1     = (const float*)d_in[27];
    const float* W2     = (const float*)d_in[28];
    const float* b2     = (const float*)d_in[29];
    const float* g1     = (const float*)d_in[30];
    const float* beta1  = (const float*)d_in[31];
    float* out = (float*)d_out;

    pack_kernel<<<192, 256>>>(Wq, bq, Wk, bk, Wv, bv,
                              Wcq, bcq, Wck, bck, Wcv, bcv,
                              gQE, betaQE, gKE, betaKE, gVE, betaVE,
                              gQH, betaQH, gKH, betaKH, gVH, betaVH,
                              W1, W2);
    proj_kernel<<<NTOK/32, 256>>>(state, H);
    attn_kernel<<<B_*2, 320>>>(state);
    ffn_kernel<<<NTOK/64, 256>>>(b1, b2, g1, beta1, out);
}

// round 15
// speedup vs baseline: 1.0343x; 1.0343x over previous
#include <cuda_runtime.h>
#include <cuda_fp16.h>
#include <cstdint>
#include <stdint.h>
#include <math.h>

#define B_    256
#define S_    300
#define NTOK  (B_*S_)        // 76800

// ---------------- scratch (__device__ globals) ------------------------------
__device__ __align__(16) __half g_q [((size_t)NTOK+16)*64];
__device__ __align__(16) __half g_k [((size_t)NTOK+16)*64];
__device__ __align__(16) __half g_v [((size_t)NTOK+16)*64];
__device__ __align__(16) float  g_z1[(size_t)NTOK*64];

// fragment-order fp16 weight streams: [ntile][lane][kstep][{b0,b1}] (half2 units)
__device__ __align__(16) __half2 g_WEf[24*32*4*2];    // 192 cols, K=64
__device__ __align__(16) __half2 g_WHf[24*32*16*2];   // 192 cols, K=256
__device__ __align__(16) __half2 g_W1f[32*32*4*2];    // 256 cols, K=64
__device__ __align__(16) __half2 g_W2f[ 8*32*16*2];   // 64 cols,  K=256

__device__ float g_bE[192], g_gE[192], g_betaE[192];
__device__ float g_bH[192], g_gH[192], g_betaH[192];

// ---------------- mma / ldmatrix helpers ------------------------------------
__device__ __forceinline__ void mma_f16(float* d, const unsigned int* a,
                                        unsigned int b0, unsigned int b1) {
    asm volatile(
        "mma.sync.aligned.m16n8k16.row.col.f32.f16.f16.f32 "
        "{%0,%1,%2,%3}, {%4,%5,%6,%7}, {%8,%9}, {%0,%1,%2,%3};\n"
        : "+f"(d[0]), "+f"(d[1]), "+f"(d[2]), "+f"(d[3])
        : "r"(a[0]), "r"(a[1]), "r"(a[2]), "r"(a[3]), "r"(b0), "r"(b1));
}
__device__ __forceinline__ void ldsm4(unsigned int* a, const void* p) {
    unsigned int s = (unsigned int)__cvta_generic_to_shared(p);
    asm volatile("ldmatrix.sync.aligned.m8n8.x4.shared.b16 {%0,%1,%2,%3}, [%4];\n"
        : "=r"(a[0]), "=r"(a[1]), "=r"(a[2]), "=r"(a[3]) : "r"(s));
}
__device__ __forceinline__ void ldsm4t(unsigned int* a, const void* p) {
    unsigned int s = (unsigned int)__cvta_generic_to_shared(p);
    asm volatile("ldmatrix.sync.aligned.m8n8.x4.trans.shared.b16 {%0,%1,%2,%3}, [%4];\n"
        : "=r"(a[0]), "=r"(a[1]), "=r"(a[2]), "=r"(a[3]) : "r"(s));
}
__device__ __forceinline__ unsigned int h2u(__half2 h) {
    return *(unsigned int*)&h;
}
// shifted softmax exp: exact (uniform shift cancels in p/l); clamp prevents
// fp16 inf (max p = e^10 = 22026 < 65504).
__device__ __forceinline__ float sexp(float s) {
    return __expf(fminf(s, 18.0f) - 8.0f);
}

// ---------------- K0: pack weights into fragment streams --------------------
__global__ void pack_kernel(
    const float* __restrict__ Wq,  const float* __restrict__ bq,
    const float* __restrict__ Wk,  const float* __restrict__ bk,
    const float* __restrict__ Wv,  const float* __restrict__ bv,
    const float* __restrict__ Wcq, const float* __restrict__ bcq,
    const float* __restrict__ Wck, const float* __restrict__ bck,
    const float* __restrict__ Wcv, const float* __restrict__ bcv,
    const float* __restrict__ gQE, const float* __restrict__ betaQE,
    const float* __restrict__ gKE, const float* __restrict__ betaKE,
    const float* __restrict__ gVE, const float* __restrict__ betaVE,
    const float* __restrict__ gQH, const float* __restrict__ betaQH,
    const float* __restrict__ gKH, const float* __restrict__ betaKH,
    const float* __restrict__ gVH, const float* __restrict__ betaVH,
    const float* __restrict__ W1,  const float* __restrict__ W2)
{
    const int tid0 = blockIdx.x * blockDim.x + threadIdx.x;
    const int stride = gridDim.x * blockDim.x;

    for (int idx = tid0; idx < 24*32*4*2; idx += stride) {
        int j = idx & 1, ks = (idx >> 1) & 3, l = (idx >> 3) & 31, nt = idx >> 8;
        int g = l >> 2, t = l & 3;
        int c = nt*8 + g;
        int k = ks*16 + 2*t + j*8;
        int br = c >> 6, cc = c & 63;
        const float* W = (br == 0) ? Wq : (br == 1) ? Wk : Wv;
        g_WEf[idx] = __floats2half2_rn(W[k*64 + cc], W[(k+1)*64 + cc]);
    }
    for (int idx = tid0; idx < 24*32*16*2; idx += stride) {
        int j = idx & 1, ks = (idx >> 1) & 15, l = (idx >> 5) & 31, nt = idx >> 10;
        int g = l >> 2, t = l & 3;
        int c = nt*8 + g;
        int k = ks*16 + 2*t + j*8;
        int br = c >> 6, cc = c & 63;
        const float* W = (br == 0) ? Wcq : (br == 1) ? Wck : Wcv;
        g_WHf[idx] = __floats2half2_rn(W[k*64 + cc], W[(k+1)*64 + cc]);
    }
    for (int idx = tid0; idx < 32*32*4*2; idx += stride) {
        int j = idx & 1, ks = (idx >> 1) & 3, l = (idx >> 3) & 31, nt = idx >> 8;
        int g = l >> 2, t = l & 3;
        int c = nt*8 + g;
        int k = ks*16 + 2*t + j*8;
        g_W1f[idx] = __floats2half2_rn(W1[k*256 + c], W1[(k+1)*256 + c]);
    }
    for (int idx = tid0; idx < 8*32*16*2; idx += stride) {
        int j = idx & 1, ks = (idx >> 1) & 15, l = (idx >> 5) & 31, nt = idx >> 10;
        int g = l >> 2, t = l & 3;
        int c = nt*8 + g;
        int k = ks*16 + 2*t + j*8;
        g_W2f[idx] = __floats2half2_rn(W2[k*64 + c], W2[(k+1)*64 + c]);
    }
    for (int c = tid0; c < 192; c += stride) {
        int br = c >> 6, j = c & 63;
        g_bE[c]    = ((br==0)?bq    :(br==1)?bk    :bv    )[j];
        g_bH[c]    = ((br==0)?bcq   :(br==1)?bck   :bcv   )[j];
        g_gE[c]    = ((br==0)?gQE   :(br==1)?gKE   :gVE   )[j];
        g_betaE[c] = ((br==0)?betaQE:(br==1)?betaKE:betaVE)[j];
        g_gH[c]    = ((br==0)?gQH   :(br==1)?gKH   :gVH   )[j];
        g_betaH[c] = ((br==0)?betaQH:(br==1)?betaKH:betaVH)[j];
    }
}

// ---------------- K1: gated projections via mma (32 tok/block, reg LN) ------
#define XR 72
#define HR 264
__global__ __launch_bounds__(256)
void proj_kernel(const float* __restrict__ state, const float* __restrict__ Hin)
{
    __shared__ __align__(16) __half Xs[32*XR];        // 4.5 KB
    __shared__ __align__(16) __half Hs[32*HR];        // 16.5 KB
    __shared__ float sP[2][32][24][2];                // 12 KB
    __shared__ float sStat[2][32][3][2];              // 1.5 KB
    const int tid = threadIdx.x;
    const size_t tok0 = (size_t)blockIdx.x * 32;

    #pragma unroll
    for (int it = 0; it < 2; it++) {
        int idx = (tid + 256*it) * 4;
        int r = idx >> 6, c = idx & 63;
        float4 f = *(const float4*)(state + (tok0 + r)*64 + c);
        *(__half2*)(Xs + r*XR + c)     = __floats2half2_rn(f.x, f.y);
        *(__half2*)(Xs + r*XR + c + 2) = __floats2half2_rn(f.z, f.w);
    }
    #pragma unroll
    for (int it = 0; it < 8; it++) {
        int idx = (tid + 256*it) * 4;
        int rh = idx >> 8, ch = idx & 255;
        float4 fh = *(const float4*)(Hin + (tok0 + rh)*256 + ch);
        *(__half2*)(Hs + rh*HR + ch)     = __floats2half2_rn(fh.x, fh.y);
        *(__half2*)(Hs + rh*HR + ch + 2) = __floats2half2_rn(fh.z, fh.w);
    }
    __syncthreads();

    const int w = tid >> 5, l = tid & 31;
    const int g = l >> 2, t = l & 3;
    const int ldrow = (l & 15), ldcol = (l >> 4) * 8;

    float accE[2][3][4];
    #pragma unroll
    for (int mt = 0; mt < 2; mt++)
        #pragma unroll
        for (int nt = 0; nt < 3; nt++)
            #pragma unroll
            for (int i = 0; i < 4; i++) accE[mt][nt][i] = 0.f;
    #pragma unroll
    for (int ksp = 0; ksp < 2; ksp++) {
        unsigned int a0[8], a1[8];
        ldsm4(a0,     Xs + ldrow*XR + ksp*32 + ldcol);
        ldsm4(a0 + 4, Xs + ldrow*XR + ksp*32 + 16 + ldcol);
        ldsm4(a1,     Xs + (16 + ldrow)*XR + ksp*32 + ldcol);
        ldsm4(a1 + 4, Xs + (16 + ldrow)*XR + ksp*32 + 16 + ldcol);
        #pragma unroll
        for (int nt = 0; nt < 3; nt++) {
            const uint4 bfrag = *(const uint4*)&g_WEf[(((w*3 + nt)*32 + l)*4 + ksp*2)*2];
            mma_f16(accE[0][nt], a0,     bfrag.x, bfrag.y);
            mma_f16(accE[0][nt], a0 + 4, bfrag.z, bfrag.w);
            mma_f16(accE[1][nt], a1,     bfrag.x, bfrag.y);
            mma_f16(accE[1][nt], a1 + 4, bfrag.z, bfrag.w);
        }
    }

    float accH[2][3][4];
    #pragma unroll
    for (int mt = 0; mt < 2; mt++)
        #pragma unroll
        for (int nt = 0; nt < 3; nt++)
            #pragma unroll
            for (int i = 0; i < 4; i++) accH[mt][nt][i] = 0.f;
    #pragma unroll
    for (int ksp = 0; ksp < 8; ksp++) {
        unsigned int a0[8], a1[8];
        ldsm4(a0,     Hs + ldrow*HR + ksp*32 + ldcol);
        ldsm4(a0 + 4, Hs + ldrow*HR + ksp*32 + 16 + ldcol);
        ldsm4(a1,     Hs + (16 + ldrow)*HR + ksp*32 + ldcol);
        ldsm4(a1 + 4, Hs + (16 + ldrow)*HR + ksp*32 + 16 + ldcol);
        #pragma unroll
        for (int nt = 0; nt < 3; nt++) {
            const uint4 bfrag = *(const uint4*)&g_WHf[(((w*3 + nt)*32 + l)*16 + ksp*2)*2];
            mma_f16(accH[0][nt], a0,     bfrag.x, bfrag.y);
            mma_f16(accH[0][nt], a0 + 4, bfrag.z, bfrag.w);
            mma_f16(accH[1][nt], a1,     bfrag.x, bfrag.y);
            mma_f16(accH[1][nt], a1 + 4, bfrag.z, bfrag.w);
        }
    }

    #pragma unroll
    for (int nt = 0; nt < 3; nt++) {
        int c0 = w*24 + nt*8 + 2*t;
        float be0 = g_bE[c0], be1 = g_bE[c0 + 1];
        float bh0 = g_bH[c0], bh1 = g_bH[c0 + 1];
        #pragma unroll
        for (int mt = 0; mt < 2; mt++) {
            accE[mt][nt][0] += be0; accE[mt][nt][1] += be1;
            accE[mt][nt][2] += be0; accE[mt][nt][3] += be1;
            accH[mt][nt][0] += bh0; accH[mt][nt][1] += bh1;
            accH[mt][nt][2] += bh0; accH[mt][nt][3] += bh1;
        }
    }

    #pragma unroll
    for (int mt = 0; mt < 2; mt++) {
        #pragma unroll
        for (int nt = 0; nt < 3; nt++) {
            int tile = w*3 + nt;
            float e1a = accE[mt][nt][0] + accE[mt][nt][1];
            float e2a = fmaf(accE[mt][nt][0], accE[mt][nt][0], accE[mt][nt][1]*accE[mt][nt][1]);
            float e1b = accE[mt][nt][2] + accE[mt][nt][3];
            float e2b = fmaf(accE[mt][nt][2], accE[mt][nt][2], accE[mt][nt][3]*accE[mt][nt][3]);
            float h1a = accH[mt][nt][0] + accH[mt][nt][1];
            float h2a = fmaf(accH[mt][nt][0], accH[mt][nt][0], accH[mt][nt][1]*accH[mt][nt][1]);
            float h1b = accH[mt][nt][2] + accH[mt][nt][3];
            float h2b = fmaf(accH[mt][nt][2], accH[mt][nt][2], accH[mt][nt][3]*accH[mt][nt][3]);
            #pragma unroll
            for (int off = 1; off <= 2; off <<= 1) {
                e1a += __shfl_xor_sync(0xffffffffu, e1a, off);
                e2a += __shfl_xor_sync(0xffffffffu, e2a, off);
                e1b += __shfl_xor_sync(0xffffffffu, e1b, off);
                e2b += __shfl_xor_sync(0xffffffffu, e2b, off);
                h1a += __shfl_xor_sync(0xffffffffu, h1a, off);
                h2a += __shfl_xor_sync(0xffffffffu, h2a, off);
                h1b += __shfl_xor_sync(0xffffffffu, h1b, off);
                h2b += __shfl_xor_sync(0xffffffffu, h2b, off);
            }
            if (t == 0) {
                int r0 = mt*16 + g, r1 = r0 + 8;
                sP[0][r0][tile][0] = e1a; sP[0][r0][tile][1] = e2a;
                sP[0][r1][tile][0] = e1b; sP[0][r1][tile][1] = e2b;
                sP[1][r0][tile][0] = h1a; sP[1][r0][tile][1] = h2a;
                sP[1][r1][tile][0] = h1b; sP[1][r1][tile][1] = h2b;
            }
        }
    }
    __syncthreads();

    if (tid < 192) {
        int eh = tid / 96, rem = tid % 96;
        int row = rem / 3, br = rem % 3;
        float s1 = 0.f, s2 = 0.f;
        #pragma unroll
        for (int tt = 0; tt < 8; tt++) {
            s1 += sP[eh][row][br*8 + tt][0];
            s2 += sP[eh][row][br*8 + tt][1];
        }
        float m = s1 * (1.f/64.f);
        float r = rsqrtf(s2*(1.f/64.f) - m*m + 1e-5f);
        sStat[eh][row][br][0] = m;
        sStat[eh][row][br][1] = r;
    }
    __syncthreads();

    #pragma unroll
    for (int nt = 0; nt < 3; nt++) {
        int tile = w*3 + nt;
        int br = tile >> 3;
        int c0 = w*24 + nt*8 + 2*t;
        float gE0 = g_gE[c0],    gE1 = g_gE[c0+1];
        float tE0 = g_betaE[c0], tE1 = g_betaE[c0+1];
        float gH0 = g_gH[c0],    gH1 = g_gH[c0+1];
        float tH0 = g_betaH[c0], tH1 = g_betaH[c0+1];
        __half* dst = (br == 0) ? g_q : (br == 1) ? g_k : g_v;
        int fc = c0 - br*64;
        #pragma unroll
        for (int mt = 0; mt < 2; mt++) {
            #pragma unroll
            for (int rh = 0; rh < 2; rh++) {
                int row = mt*16 + g + rh*8;
                float mE = sStat[0][row][br][0], rE = sStat[0][row][br][1];
                float mH = sStat[1][row][br][0], rH = sStat[1][row][br][1];
                float e0 = (accE[mt][nt][rh*2]     - mE)*rE*gE0 + tE0;
                float e1 = (accE[mt][nt][rh*2 + 1] - mE)*rE*gE1 + tE1;
                float h0 = (accH[mt][nt][rh*2]     - mH)*rH*gH0 + tH0;
                float h1 = (accH[mt][nt][rh*2 + 1] - mH)*rH*gH1 + tH1;
                *(__half2*)&dst[(tok0 + row)*64 + fc] = __floats2half2_rn(e0*h0, e1*h1);
            }
        }
    }
}

// ---------------- K2: flash attention via mma + residual -> Z1 --------------
#define KR 40
__global__ __launch_bounds__(320, 2)
void attn_kernel(const float* __restrict__ state)
{
    __shared__ __align__(16) __half Ks[304*KR];
    __shared__ __align__(16) __half Vs[304*KR];
    const int tid = threadIdx.x;
    const int b = blockIdx.x >> 1, h = blockIdx.x & 1;
    const size_t bTok = (size_t)b * S_;
    const int hoff = h * 32;

    // stage K/V with 16B vectors; zero pad rows 300..303
    for (int idx = tid; idx < 304*4; idx += 320) {
        int row = idx >> 2, seg = idx & 3;
        uint4 kv = make_uint4(0u,0u,0u,0u), vv = make_uint4(0u,0u,0u,0u);
        if (row < S_) {
            kv = *(const uint4*)&g_k[(bTok + row)*64 + hoff + seg*8];
            vv = *(const uint4*)&g_v[(bTok + row)*64 + hoff + seg*8];
        }
        *(uint4*)&Ks[row*KR + seg*8] = kv;
        *(uint4*)&Vs[row*KR + seg*8] = vv;
    }
    __syncthreads();

    const int w = tid >> 5, l = tid & 31;
    const int g = l >> 2, t = l & 3;
    const int qt0 = (2*w   < 19) ? 2*w   : 18;
    const int qt1 = (2*w+1 < 19) ? 2*w+1 : 18;
    const int q0a = qt0*16, q0b = qt1*16;

    unsigned int aq[2][2][4];
    #pragma unroll
    for (int qi = 0; qi < 2; qi++) {
        int q0 = qi ? q0b : q0a;
        #pragma unroll
        for (int ks = 0; ks < 2; ks++) {
            const __half* r0p = g_q + (bTok + q0 + g    )*64 + hoff + ks*16 + 2*t;
            const __half* r1p = g_q + (bTok + q0 + g + 8)*64 + hoff + ks*16 + 2*t;
            aq[qi][ks][0] = *(const unsigned int*)r0p;
            aq[qi][ks][1] = *(const unsigned int*)r1p;
            aq[qi][ks][2] = *(const unsigned int*)(r0p + 8);
            aq[qi][ks][3] = *(const unsigned int*)(r1p + 8);
        }
    }

    float out[2][4][4];
    float lsum[2][2];
    #pragma unroll
    for (int qi = 0; qi < 2; qi++) {
        lsum[qi][0] = 0.f; lsum[qi][1] = 0.f;
        #pragma unroll
        for (int nt = 0; nt < 4; nt++)
            #pragma unroll
            for (int i = 0; i < 4; i++) out[qi][nt][i] = 0.f;
    }

    const float SC = 0.17677669529663687f;   // 1/sqrt(32)

    for (int kc = 0; kc < 19; kc++) {
        unsigned int kb0[4], kb1[4];
        ldsm4(kb0, Ks + (kc*16 +     (l & 7))*KR + (l >> 3)*8);
        ldsm4(kb1, Ks + (kc*16 + 8 + (l & 7))*KR + (l >> 3)*8);
        unsigned int vb[8];
        ldsm4t(vb,     Vs + (kc*16 + ((l >> 3) & 1)*8 + (l & 7))*KR + (l >> 4)*8);
        ldsm4t(vb + 4, Vs + (kc*16 + ((l >> 3) & 1)*8 + (l & 7))*KR + 16 + (l >> 4)*8);

        #pragma unroll
        for (int qi = 0; qi < 2; qi++) {
            float sc0[4] = {0.f,0.f,0.f,0.f};
            float sc1[4] = {0.f,0.f,0.f,0.f};
            mma_f16(sc0, aq[qi][0], kb0[0], kb0[1]);
            mma_f16(sc0, aq[qi][1], kb0[2], kb0[3]);
            mma_f16(sc1, aq[qi][0], kb1[0], kb1[1]);
            mma_f16(sc1, aq[qi][1], kb1[2], kb1[3]);

            float p00 = sexp(sc0[0]*SC), p01 = sexp(sc0[1]*SC);
            float p02 = sexp(sc0[2]*SC), p03 = sexp(sc0[3]*SC);
            float p10 = sexp(sc1[0]*SC), p11 = sexp(sc1[1]*SC);
            float p12 = sexp(sc1[2]*SC), p13 = sexp(sc1[3]*SC);
            if (kc == 18 && t >= 2) {
                p10 = 0.f; p11 = 0.f; p12 = 0.f; p13 = 0.f;
            }
            lsum[qi][0] += (p00 + p01) + (p10 + p11);
            lsum[qi][1] += (p02 + p03) + (p12 + p13);

            unsigned int pf[4];
            pf[0] = h2u(__floats2half2_rn(p00, p01));
            pf[1] = h2u(__floats2half2_rn(p02, p03));
            pf[2] = h2u(__floats2half2_rn(p10, p11));
            pf[3] = h2u(__floats2half2_rn(p12, p13));

            mma_f16(out[qi][0], pf, vb[0], vb[1]);
            mma_f16(out[qi][1], pf, vb[2], vb[3]);
            mma_f16(out[qi][2], pf, vb[4], vb[5]);
            mma_f16(out[qi][3], pf, vb[6], vb[7]);
        }
    }

    #pragma unroll
    for (int qi = 0; qi < 2; qi++) {
        int q0 = qi ? q0b : q0a;
        float l0 = lsum[qi][0], l1 = lsum[qi][1];
        l0 += __shfl_xor_sync(0xffffffffu, l0, 1);
        l0 += __shfl_xor_sync(0xffffffffu, l0, 2);
        l1 += __shfl_xor_sync(0xffffffffu, l1, 1);
        l1 += __shfl_xor_sync(0xffffffffu, l1, 2);
        float inv0 = 1.f / l0, inv1 = 1.f / l1;
        size_t r0 = bTok + q0 + g;
        size_t r1 = r0 + 8;
        bool wr1 = (q0 + g + 8) < S_;
        #pragma unroll
        for (int nt = 0; nt < 4; nt++) {
            int c = hoff + nt*8 + 2*t;
            float2 s0 = *(const float2*)&state[r0*64 + c];
            float2 o0;
            o0.x = fmaf(out[qi][nt][0], inv0, s0.x);
            o0.y = fmaf(out[qi][nt][1], inv0, s0.y);
            *(float2*)&g_z1[r0*64 + c] = o0;
            if (wr1) {
                float2 s1 = *(const float2*)&state[r1*64 + c];
                float2 o1;
                o1.x = fmaf(out[qi][nt][2], inv1, s1.x);
                o1.y = fmaf(out[qi][nt][3], inv1, s1.y);
                *(float2*)&g_z1[r1*64 + c] = o1;
            }
        }
    }
}

// ---------------- K3: LN -> FFN(gelu) -> +Z1 via mma (32 tok/block) ---------
#define ZR  72
#define H3R 264
#define Z1R 68
__global__ __launch_bounds__(256)
void ffn_kernel(const float* __restrict__ b1, const float* __restrict__ b2,
                const float* __restrict__ g1, const float* __restrict__ beta1,
                float* __restrict__ out)
{
    __shared__ __align__(16) __half Z2s[32*ZR];
    __shared__ __align__(16) __half H3s[32*H3R];
    __shared__ __align__(16) float  Z1s[32*Z1R];
    const int tid = threadIdx.x;
    const size_t tok0 = (size_t)blockIdx.x * 32;

    {
        int tk = tid >> 3, sg = tid & 7;
        const float* src = g_z1 + (tok0 + tk)*64 + sg*8;
        float4 f0 = *(const float4*)src;
        float4 f1 = *(const float4*)(src + 4);
        float v[8] = {f0.x, f0.y, f0.z, f0.w, f1.x, f1.y, f1.z, f1.w};
        float s1 = 0.f, s2 = 0.f;
        #pragma unroll
        for (int u = 0; u < 8; u++) { s1 += v[u]; s2 = fmaf(v[u], v[u], s2); }
        #pragma unroll
        for (int off = 1; off <= 4; off <<= 1) {
            s1 += __shfl_xor_sync(0xffffffffu, s1, off);
            s2 += __shfl_xor_sync(0xffffffffu, s2, off);
        }
        float m = s1 * (1.f/64.f);
        float r = rsqrtf(s2*(1.f/64.f) - m*m + 1e-5f);
        *(float4*)(Z1s + tk*Z1R + sg*8)     = f0;
        *(float4*)(Z1s + tk*Z1R + sg*8 + 4) = f1;
        #pragma unroll
        for (int u = 0; u < 8; u += 2) {
            int c = sg*8 + u;
            float a0 = (v[u]   - m)*r*g1[c]   + beta1[c];
            float a1 = (v[u+1] - m)*r*g1[c+1] + beta1[c+1];
            *(__half2*)(Z2s + tk*ZR + c) = __floats2half2_rn(a0, a1);
        }
    }
    __syncthreads();

    const int w = tid >> 5, l = tid & 31;
    const int g = l >> 2, t = l & 3;
    const int ldrow = (l & 15), ldcol = (l >> 4) * 8;
    const int mt = w & 1;

    {
        const int cq = w >> 1;
        float acc1[8][4];
        #pragma unroll
        for (int nt = 0; nt < 8; nt++)
            #pragma unroll
            for (int i = 0; i < 4; i++) acc1[nt][i] = 0.f;
        #pragma unroll
        for (int ksp = 0; ksp < 2; ksp++) {
            unsigned int a[8];
            ldsm4(a,     Z2s + (mt*16 + ldrow)*ZR + ksp*32 + ldcol);
            ldsm4(a + 4, Z2s + (mt*16 + ldrow)*ZR + ksp*32 + 16 + ldcol);
            #pragma unroll
            for (int nt = 0; nt < 8; nt++) {
                const uint4 bfrag = *(const uint4*)&g_W1f[(((cq*8 + nt)*32 + l)*4 + ksp*2)*2];
                mma_f16(acc1[nt], a,     bfrag.x, bfrag.y);
                mma_f16(acc1[nt], a + 4, bfrag.z, bfrag.w);
            }
        }
        #pragma unroll
        for (int nt = 0; nt < 8; nt++) {
            int c0 = cq*64 + nt*8 + 2*t;
            float bb0 = b1[c0], bb1 = b1[c0 + 1];
            float x0 = acc1[nt][0] + bb0, x1 = acc1[nt][1] + bb1;
            float x2 = acc1[nt][2] + bb0, x3 = acc1[nt][3] + bb1;
            x0 = 0.5f*x0*(1.f + erff(x0*0.70710678118654752f));
            x1 = 0.5f*x1*(1.f + erff(x1*0.70710678118654752f));
            x2 = 0.5f*x2*(1.f + erff(x2*0.70710678118654752f));
            x3 = 0.5f*x3*(1.f + erff(x3*0.70710678118654752f));
            *(__half2*)(H3s + (mt*16 + g)*H3R + c0)     = __floats2half2_rn(x0, x1);
            *(__half2*)(H3s + (mt*16 + g + 8)*H3R + c0) = __floats2half2_rn(x2, x3);
        }
    }
    __syncthreads();

    {
        const int np = w >> 1;
        float acc2[2][4];
        #pragma unroll
        for (int nt = 0; nt < 2; nt++)
            #pragma unroll
            for (int i = 0; i < 4; i++) acc2[nt][i] = 0.f;
        #pragma unroll
        for (int ksp = 0; ksp < 8; ksp++) {
            unsigned int a[8];
            ldsm4(a,     H3s + (mt*16 + ldrow)*H3R + ksp*32 + ldcol);
            ldsm4(a + 4, H3s + (mt*16 + ldrow)*H3R + ksp*32 + 16 + ldcol);
            #pragma unroll
            for (int nt = 0; nt < 2; nt++) {
                const uint4 bfrag = *(const uint4*)&g_W2f[(((np*2 + nt)*32 + l)*16 + ksp*2)*2];
                mma_f16(acc2[nt], a,     bfrag.x, bfrag.y);
                mma_f16(acc2[nt], a + 4, bfrag.z, bfrag.w);
            }
        }
        #pragma unroll
        for (int nt = 0; nt < 2; nt++) {
            int c0 = np*16 + nt*8 + 2*t;
            int r0 = mt*16 + g;
            float bb0 = b2[c0], bb1 = b2[c0 + 1];
            out[(tok0 + r0)*64 + c0]       = acc2[nt][0] + bb0 + Z1s[r0*Z1R + c0];
            out[(tok0 + r0)*64 + c0 + 1]   = acc2[nt][1] + bb1 + Z1s[r0*Z1R + c0 + 1];
            out[(tok0 + r0 + 8)*64 + c0]   = acc2[nt][2] + bb0 + Z1s[(r0+8)*Z1R + c0];
            out[(tok0 + r0 + 8)*64 + c0+1] = acc2[nt][3] + bb1 + Z1s[(r0+8)*Z1R + c0 + 1];
        }
    }
}

// ---------------- launcher --------------------------------------------------
extern "C" void kernel_launch(void* const* d_in, const int* in_sizes, int n_in,
                              void* d_out, int out_size)
{
    const float* state  = (const float*)d_in[0];
    const float* H      = (const float*)d_in[1];
    const float* Wq     = (const float*)d_in[2];
    const float* bq     = (const float*)d_in[3];
    const float* Wk     = (const float*)d_in[4];
    const float* bk     = (const float*)d_in[5];
    const float* Wv     = (const float*)d_in[6];
    const float* bv     = (const float*)d_in[7];
    const float* Wcq    = (const float*)d_in[8];
    const float* bcq    = (const float*)d_in[9];
    const float* Wck    = (const float*)d_in[10];
    const float* bck    = (const float*)d_in[11];
    const float* Wcv    = (const float*)d_in[12];
    const float* bcv    = (const float*)d_in[13];
    const float* gQE    = (const float*)d_in[14];
    const float* betaQE = (const float*)d_in[15];
    const float* gKE    = (const float*)d_in[16];
    const float* betaKE = (const float*)d_in[17];
    const float* gVE    = (const float*)d_in[18];
    const float* betaVE = (const float*)d_in[19];
    const float* gQH    = (const float*)d_in[20];
    const float* betaQH = (const float*)d_in[21];
    const float* gKH    = (const float*)d_in[22];
    const float* betaKH = (const float*)d_in[23];
    const float* gVH    = (const float*)d_in[24];
    const float* betaVH = (const float*)d_in[25];
    const float* W1     = (const float*)d_in[26];
    const float* b1     = (const float*)d_in[27];
    const float* W2     = (const float*)d_in[28];
    const float* b2     = (const float*)d_in[29];
    const float* g1     = (const float*)d_in[30];
    const float* beta1  = (const float*)d_in[31];
    float* out = (float*)d_out;

    pack_kernel<<<192, 256>>>(Wq, bq, Wk, bk, Wv, bv,
                              Wcq, bcq, Wck, bck, Wcv, bcv,
                              gQE, betaQE, gKE, betaKE, gVE, betaVE,
                              gQH, betaQH, gKH, betaKH, gVH, betaVH,
                              W1, W2);
    proj_kernel<<<NTOK/32, 256>>>(state, H);
    attn_kernel<<<B_*2, 320>>>(state);
    ffn_kernel<<<NTOK/32, 256>>>(b1, b2, g1, beta1, out);
}

// round 16
// speedup vs baseline: 1.0418x; 1.0073x over previous
#include <cuda_runtime.h>
#include <cuda_fp16.h>
#include <cstdint>
#include <stdint.h>
#include <math.h>

#define B_    256
#define S_    300
#define NTOK  (B_*S_)        // 76800

// ---------------- scratch (__device__ globals) ------------------------------
__device__ __align__(16) __half g_q [((size_t)NTOK+16)*64];
__device__ __align__(16) __half g_k [((size_t)NTOK+16)*64];
__device__ __align__(16) __half g_v [((size_t)NTOK+16)*64];
__device__ __align__(16) float  g_z1[(size_t)NTOK*64];

// fragment-order fp16 weight streams: [ntile][lane][kstep][{b0,b1}] (half2 units)
__device__ __align__(16) __half2 g_WEf[24*32*4*2];    // 192 cols, K=64
__device__ __align__(16) __half2 g_WHf[24*32*16*2];   // 192 cols, K=256
__device__ __align__(16) __half2 g_W1f[32*32*4*2];    // 256 cols, K=64
__device__ __align__(16) __half2 g_W2f[ 8*32*16*2];   // 64 cols,  K=256

__device__ float g_bE[192], g_gE[192], g_betaE[192];
__device__ float g_bH[192], g_gH[192], g_betaH[192];

// ---------------- mma / ldmatrix helpers ------------------------------------
__device__ __forceinline__ void mma_f16(float* d, const unsigned int* a,
                                        unsigned int b0, unsigned int b1) {
    asm volatile(
        "mma.sync.aligned.m16n8k16.row.col.f32.f16.f16.f32 "
        "{%0,%1,%2,%3}, {%4,%5,%6,%7}, {%8,%9}, {%0,%1,%2,%3};\n"
        : "+f"(d[0]), "+f"(d[1]), "+f"(d[2]), "+f"(d[3])
        : "r"(a[0]), "r"(a[1]), "r"(a[2]), "r"(a[3]), "r"(b0), "r"(b1));
}
__device__ __forceinline__ void ldsm4(unsigned int* a, const void* p) {
    unsigned int s = (unsigned int)__cvta_generic_to_shared(p);
    asm volatile("ldmatrix.sync.aligned.m8n8.x4.shared.b16 {%0,%1,%2,%3}, [%4];\n"
        : "=r"(a[0]), "=r"(a[1]), "=r"(a[2]), "=r"(a[3]) : "r"(s));
}
__device__ __forceinline__ void ldsm4t(unsigned int* a, const void* p) {
    unsigned int s = (unsigned int)__cvta_generic_to_shared(p);
    asm volatile("ldmatrix.sync.aligned.m8n8.x4.trans.shared.b16 {%0,%1,%2,%3}, [%4];\n"
        : "=r"(a[0]), "=r"(a[1]), "=r"(a[2]), "=r"(a[3]) : "r"(s));
}
__device__ __forceinline__ unsigned int h2u(__half2 h) {
    return *(unsigned int*)&h;
}
// shifted softmax exp: exact (uniform shift cancels in p/l); clamp prevents
// fp16 inf (max p = e^10 = 22026 < 65504).
__device__ __forceinline__ float sexp(float s) {
    return __expf(fminf(s, 18.0f) - 8.0f);
}

// ---------------- K0: pack weights into fragment streams --------------------
__global__ void pack_kernel(
    const float* __restrict__ Wq,  const float* __restrict__ bq,
    const float* __restrict__ Wk,  const float* __restrict__ bk,
    const float* __restrict__ Wv,  const float* __restrict__ bv,
    const float* __restrict__ Wcq, const float* __restrict__ bcq,
    const float* __restrict__ Wck, const float* __restrict__ bck,
    const float* __restrict__ Wcv, const float* __restrict__ bcv,
    const float* __restrict__ gQE, const float* __restrict__ betaQE,
    const float* __restrict__ gKE, const float* __restrict__ betaKE,
    const float* __restrict__ gVE, const float* __restrict__ betaVE,
    const float* __restrict__ gQH, const float* __restrict__ betaQH,
    const float* __restrict__ gKH, const float* __restrict__ betaKH,
    const float* __restrict__ gVH, const float* __restrict__ betaVH,
    const float* __restrict__ W1,  const float* __restrict__ W2)
{
    const int tid0 = blockIdx.x * blockDim.x + threadIdx.x;
    const int stride = gridDim.x * blockDim.x;

    for (int idx = tid0; idx < 24*32*4*2; idx += stride) {
        int j = idx & 1, ks = (idx >> 1) & 3, l = (idx >> 3) & 31, nt = idx >> 8;
        int g = l >> 2, t = l & 3;
        int c = nt*8 + g;
        int k = ks*16 + 2*t + j*8;
        int br = c >> 6, cc = c & 63;
        const float* W = (br == 0) ? Wq : (br == 1) ? Wk : Wv;
        g_WEf[idx] = __floats2half2_rn(W[k*64 + cc], W[(k+1)*64 + cc]);
    }
    for (int idx = tid0; idx < 24*32*16*2; idx += stride) {
        int j = idx & 1, ks = (idx >> 1) & 15, l = (idx >> 5) & 31, nt = idx >> 10;
        int g = l >> 2, t = l & 3;
        int c = nt*8 + g;
        int k = ks*16 + 2*t + j*8;
        int br = c >> 6, cc = c & 63;
        const float* W = (br == 0) ? Wcq : (br == 1) ? Wck : Wcv;
        g_WHf[idx] = __floats2half2_rn(W[k*64 + cc], W[(k+1)*64 + cc]);
    }
    for (int idx = tid0; idx < 32*32*4*2; idx += stride) {
        int j = idx & 1, ks = (idx >> 1) & 3, l = (idx >> 3) & 31, nt = idx >> 8;
        int g = l >> 2, t = l & 3;
        int c = nt*8 + g;
        int k = ks*16 + 2*t + j*8;
        g_W1f[idx] = __floats2half2_rn(W1[k*256 + c], W1[(k+1)*256 + c]);
    }
    for (int idx = tid0; idx < 8*32*16*2; idx += stride) {
        int j = idx & 1, ks = (idx >> 1) & 15, l = (idx >> 5) & 31, nt = idx >> 10;
        int g = l >> 2, t = l & 3;
        int c = nt*8 + g;
        int k = ks*16 + 2*t + j*8;
        g_W2f[idx] = __floats2half2_rn(W2[k*64 + c], W2[(k+1)*64 + c]);
    }
    for (int c = tid0; c < 192; c += stride) {
        int br = c >> 6, j = c & 63;
        g_bE[c]    = ((br==0)?bq    :(br==1)?bk    :bv    )[j];
        g_bH[c]    = ((br==0)?bcq   :(br==1)?bck   :bcv   )[j];
        g_gE[c]    = ((br==0)?gQE   :(br==1)?gKE   :gVE   )[j];
        g_betaE[c] = ((br==0)?betaQE:(br==1)?betaKE:betaVE)[j];
        g_gH[c]    = ((br==0)?gQH   :(br==1)?gKH   :gVH   )[j];
        g_betaH[c] = ((br==0)?betaQH:(br==1)?betaKH:betaVH)[j];
    }
}

// ---------------- K1: gated projections via mma (32 tok/block, reg LN) ------
#define XR 72
#define HR 264
__global__ __launch_bounds__(256)
void proj_kernel(const float* __restrict__ state, const float* __restrict__ Hin)
{
    __shared__ __align__(16) __half Xs[32*XR];        // 4.5 KB
    __shared__ __align__(16) __half Hs[32*HR];        // 16.5 KB
    __shared__ float sP[2][32][24][2];                // 12 KB
    __shared__ float sStat[2][32][3][2];              // 1.5 KB
    const int tid = threadIdx.x;
    const size_t tok0 = (size_t)blockIdx.x * 32;

    #pragma unroll
    for (int it = 0; it < 2; it++) {
        int idx = (tid + 256*it) * 4;
        int r = idx >> 6, c = idx & 63;
        float4 f = *(const float4*)(state + (tok0 + r)*64 + c);
        *(__half2*)(Xs + r*XR + c)     = __floats2half2_rn(f.x, f.y);
        *(__half2*)(Xs + r*XR + c + 2) = __floats2half2_rn(f.z, f.w);
    }
    #pragma unroll
    for (int it = 0; it < 8; it++) {
        int idx = (tid + 256*it) * 4;
        int rh = idx >> 8, ch = idx & 255;
        float4 fh = *(const float4*)(Hin + (tok0 + rh)*256 + ch);
        *(__half2*)(Hs + rh*HR + ch)     = __floats2half2_rn(fh.x, fh.y);
        *(__half2*)(Hs + rh*HR + ch + 2) = __floats2half2_rn(fh.z, fh.w);
    }
    __syncthreads();

    const int w = tid >> 5, l = tid & 31;
    const int g = l >> 2, t = l & 3;
    const int ldrow = (l & 15), ldcol = (l >> 4) * 8;

    float accE[2][3][4];
    #pragma unroll
    for (int mt = 0; mt < 2; mt++)
        #pragma unroll
        for (int nt = 0; nt < 3; nt++)
            #pragma unroll
            for (int i = 0; i < 4; i++) accE[mt][nt][i] = 0.f;
    #pragma unroll
    for (int ksp = 0; ksp < 2; ksp++) {
        unsigned int a0[8], a1[8];
        ldsm4(a0,     Xs + ldrow*XR + ksp*32 + ldcol);
        ldsm4(a0 + 4, Xs + ldrow*XR + ksp*32 + 16 + ldcol);
        ldsm4(a1,     Xs + (16 + ldrow)*XR + ksp*32 + ldcol);
        ldsm4(a1 + 4, Xs + (16 + ldrow)*XR + ksp*32 + 16 + ldcol);
        #pragma unroll
        for (int nt = 0; nt < 3; nt++) {
            const uint4 bfrag = *(const uint4*)&g_WEf[(((w*3 + nt)*32 + l)*4 + ksp*2)*2];
            mma_f16(accE[0][nt], a0,     bfrag.x, bfrag.y);
            mma_f16(accE[0][nt], a0 + 4, bfrag.z, bfrag.w);
            mma_f16(accE[1][nt], a1,     bfrag.x, bfrag.y);
            mma_f16(accE[1][nt], a1 + 4, bfrag.z, bfrag.w);
        }
    }

    float accH[2][3][4];
    #pragma unroll
    for (int mt = 0; mt < 2; mt++)
        #pragma unroll
        for (int nt = 0; nt < 3; nt++)
            #pragma unroll
            for (int i = 0; i < 4; i++) accH[mt][nt][i] = 0.f;
    #pragma unroll
    for (int ksp = 0; ksp < 8; ksp++) {
        unsigned int a0[8], a1[8];
        ldsm4(a0,     Hs + ldrow*HR + ksp*32 + ldcol);
        ldsm4(a0 + 4, Hs + ldrow*HR + ksp*32 + 16 + ldcol);
        ldsm4(a1,     Hs + (16 + ldrow)*HR + ksp*32 + ldcol);
        ldsm4(a1 + 4, Hs + (16 + ldrow)*HR + ksp*32 + 16 + ldcol);
        #pragma unroll
        for (int nt = 0; nt < 3; nt++) {
            const uint4 bfrag = *(const uint4*)&g_WHf[(((w*3 + nt)*32 + l)*16 + ksp*2)*2];
            mma_f16(accH[0][nt], a0,     bfrag.x, bfrag.y);
            mma_f16(accH[0][nt], a0 + 4, bfrag.z, bfrag.w);
            mma_f16(accH[1][nt], a1,     bfrag.x, bfrag.y);
            mma_f16(accH[1][nt], a1 + 4, bfrag.z, bfrag.w);
        }
    }

    #pragma unroll
    for (int nt = 0; nt < 3; nt++) {
        int c0 = w*24 + nt*8 + 2*t;
        float be0 = g_bE[c0], be1 = g_bE[c0 + 1];
        float bh0 = g_bH[c0], bh1 = g_bH[c0 + 1];
        #pragma unroll
        for (int mt = 0; mt < 2; mt++) {
            accE[mt][nt][0] += be0; accE[mt][nt][1] += be1;
            accE[mt][nt][2] += be0; accE[mt][nt][3] += be1;
            accH[mt][nt][0] += bh0; accH[mt][nt][1] += bh1;
            accH[mt][nt][2] += bh0; accH[mt][nt][3] += bh1;
        }
    }

    #pragma unroll
    for (int mt = 0; mt < 2; mt++) {
        #pragma unroll
        for (int nt = 0; nt < 3; nt++) {
            int tile = w*3 + nt;
            float e1a = accE[mt][nt][0] + accE[mt][nt][1];
            float e2a = fmaf(accE[mt][nt][0], accE[mt][nt][0], accE[mt][nt][1]*accE[mt][nt][1]);
            float e1b = accE[mt][nt][2] + accE[mt][nt][3];
            float e2b = fmaf(accE[mt][nt][2], accE[mt][nt][2], accE[mt][nt][3]*accE[mt][nt][3]);
            float h1a = accH[mt][nt][0] + accH[mt][nt][1];
            float h2a = fmaf(accH[mt][nt][0], accH[mt][nt][0], accH[mt][nt][1]*accH[mt][nt][1]);
            float h1b = accH[mt][nt][2] + accH[mt][nt][3];
            float h2b = fmaf(accH[mt][nt][2], accH[mt][nt][2], accH[mt][nt][3]*accH[mt][nt][3]);
            #pragma unroll
            for (int off = 1; off <= 2; off <<= 1) {
                e1a += __shfl_xor_sync(0xffffffffu, e1a, off);
                e2a += __shfl_xor_sync(0xffffffffu, e2a, off);
                e1b += __shfl_xor_sync(0xffffffffu, e1b, off);
                e2b += __shfl_xor_sync(0xffffffffu, e2b, off);
                h1a += __shfl_xor_sync(0xffffffffu, h1a, off);
                h2a += __shfl_xor_sync(0xffffffffu, h2a, off);
                h1b += __shfl_xor_sync(0xffffffffu, h1b, off);
                h2b += __shfl_xor_sync(0xffffffffu, h2b, off);
            }
            if (t == 0) {
                int r0 = mt*16 + g, r1 = r0 + 8;
                sP[0][r0][tile][0] = e1a; sP[0][r0][tile][1] = e2a;
                sP[0][r1][tile][0] = e1b; sP[0][r1][tile][1] = e2b;
                sP[1][r0][tile][0] = h1a; sP[1][r0][tile][1] = h2a;
                sP[1][r1][tile][0] = h1b; sP[1][r1][tile][1] = h2b;
            }
        }
    }
    __syncthreads();

    if (tid < 192) {
        int eh = tid / 96, rem = tid % 96;
        int row = rem / 3, br = rem % 3;
        float s1 = 0.f, s2 = 0.f;
        #pragma unroll
        for (int tt = 0; tt < 8; tt++) {
            s1 += sP[eh][row][br*8 + tt][0];
            s2 += sP[eh][row][br*8 + tt][1];
        }
        float m = s1 * (1.f/64.f);
        float r = rsqrtf(s2*(1.f/64.f) - m*m + 1e-5f);
        sStat[eh][row][br][0] = m;
        sStat[eh][row][br][1] = r;
    }
    __syncthreads();

    #pragma unroll
    for (int nt = 0; nt < 3; nt++) {
        int tile = w*3 + nt;
        int br = tile >> 3;
        int c0 = w*24 + nt*8 + 2*t;
        float gE0 = g_gE[c0],    gE1 = g_gE[c0+1];
        float tE0 = g_betaE[c0], tE1 = g_betaE[c0+1];
        float gH0 = g_gH[c0],    gH1 = g_gH[c0+1];
        float tH0 = g_betaH[c0], tH1 = g_betaH[c0+1];
        __half* dst = (br == 0) ? g_q : (br == 1) ? g_k : g_v;
        int fc = c0 - br*64;
        #pragma unroll
        for (int mt = 0; mt < 2; mt++) {
            #pragma unroll
            for (int rh = 0; rh < 2; rh++) {
                int row = mt*16 + g + rh*8;
                float mE = sStat[0][row][br][0], rE = sStat[0][row][br][1];
                float mH = sStat[1][row][br][0], rH = sStat[1][row][br][1];
                float e0 = (accE[mt][nt][rh*2]     - mE)*rE*gE0 + tE0;
                float e1 = (accE[mt][nt][rh*2 + 1] - mE)*rE*gE1 + tE1;
                float h0 = (accH[mt][nt][rh*2]     - mH)*rH*gH0 + tH0;
                float h1 = (accH[mt][nt][rh*2 + 1] - mH)*rH*gH1 + tH1;
                *(__half2*)&dst[(tok0 + row)*64 + fc] = __floats2half2_rn(e0*h0, e1*h1);
            }
        }
    }
}

// ---------------- K2: flash attention via mma + residual -> Z1 --------------
#define KR 40
__global__ __launch_bounds__(320, 2)
void attn_kernel(const float* __restrict__ state)
{
    __shared__ __align__(16) __half Ks[304*KR];
    __shared__ __align__(16) __half Vs[304*KR];
    const int tid = threadIdx.x;
    const int b = blockIdx.x >> 1, h = blockIdx.x & 1;
    const size_t bTok = (size_t)b * S_;
    const int hoff = h * 32;

    // stage K/V with 16B vectors; zero pad rows 300..303
    for (int idx = tid; idx < 304*4; idx += 320) {
        int row = idx >> 2, seg = idx & 3;
        uint4 kv = make_uint4(0u,0u,0u,0u), vv = make_uint4(0u,0u,0u,0u);
        if (row < S_) {
            kv = *(const uint4*)&g_k[(bTok + row)*64 + hoff + seg*8];
            vv = *(const uint4*)&g_v[(bTok + row)*64 + hoff + seg*8];
        }
        *(uint4*)&Ks[row*KR + seg*8] = kv;
        *(uint4*)&Vs[row*KR + seg*8] = vv;
    }
    __syncthreads();

    const int w = tid >> 5, l = tid & 31;
    const int g = l >> 2, t = l & 3;
    const int qt0 = (2*w   < 19) ? 2*w   : 18;
    const int qt1 = (2*w+1 < 19) ? 2*w+1 : 18;
    const int q0a = qt0*16, q0b = qt1*16;

    unsigned int aq[2][2][4];
    #pragma unroll
    for (int qi = 0; qi < 2; qi++) {
        int q0 = qi ? q0b : q0a;
        #pragma unroll
        for (int ks = 0; ks < 2; ks++) {
            const __half* r0p = g_q + (bTok + q0 + g    )*64 + hoff + ks*16 + 2*t;
            const __half* r1p = g_q + (bTok + q0 + g + 8)*64 + hoff + ks*16 + 2*t;
            aq[qi][ks][0] = *(const unsigned int*)r0p;
            aq[qi][ks][1] = *(const unsigned int*)r1p;
            aq[qi][ks][2] = *(const unsigned int*)(r0p + 8);
            aq[qi][ks][3] = *(const unsigned int*)(r1p + 8);
        }
    }

    float out[2][4][4];
    float lsum[2][2];
    #pragma unroll
    for (int qi = 0; qi < 2; qi++) {
        lsum[qi][0] = 0.f; lsum[qi][1] = 0.f;
        #pragma unroll
        for (int nt = 0; nt < 4; nt++)
            #pragma unroll
            for (int i = 0; i < 4; i++) out[qi][nt][i] = 0.f;
    }

    const float SC = 0.17677669529663687f;   // 1/sqrt(32)

    for (int kc = 0; kc < 19; kc++) {
        unsigned int kb0[4], kb1[4];
        ldsm4(kb0, Ks + (kc*16 +     (l & 7))*KR + (l >> 3)*8);
        ldsm4(kb1, Ks + (kc*16 + 8 + (l & 7))*KR + (l >> 3)*8);
        unsigned int vb[8];
        ldsm4t(vb,     Vs + (kc*16 + ((l >> 3) & 1)*8 + (l & 7))*KR + (l >> 4)*8);
        ldsm4t(vb + 4, Vs + (kc*16 + ((l >> 3) & 1)*8 + (l & 7))*KR + 16 + (l >> 4)*8);

        #pragma unroll
        for (int qi = 0; qi < 2; qi++) {
            float sc0[4] = {0.f,0.f,0.f,0.f};
            float sc1[4] = {0.f,0.f,0.f,0.f};
            mma_f16(sc0, aq[qi][0], kb0[0], kb0[1]);
            mma_f16(sc0, aq[qi][1], kb0[2], kb0[3]);
            mma_f16(sc1, aq[qi][0], kb1[0], kb1[1]);
            mma_f16(sc1, aq[qi][1], kb1[2], kb1[3]);

            float p00 = sexp(sc0[0]*SC), p01 = sexp(sc0[1]*SC);
            float p02 = sexp(sc0[2]*SC), p03 = sexp(sc0[3]*SC);
            float p10 = sexp(sc1[0]*SC), p11 = sexp(sc1[1]*SC);
            float p12 = sexp(sc1[2]*SC), p13 = sexp(sc1[3]*SC);
            if (kc == 18 && t >= 2) {
                p10 = 0.f; p11 = 0.f; p12 = 0.f; p13 = 0.f;
            }
            lsum[qi][0] += (p00 + p01) + (p10 + p11);
            lsum[qi][1] += (p02 + p03) + (p12 + p13);

            unsigned int pf[4];
            pf[0] = h2u(__floats2half2_rn(p00, p01));
            pf[1] = h2u(__floats2half2_rn(p02, p03));
            pf[2] = h2u(__floats2half2_rn(p10, p11));
            pf[3] = h2u(__floats2half2_rn(p12, p13));

            mma_f16(out[qi][0], pf, vb[0], vb[1]);
            mma_f16(out[qi][1], pf, vb[2], vb[3]);
            mma_f16(out[qi][2], pf, vb[4], vb[5]);
            mma_f16(out[qi][3], pf, vb[6], vb[7]);
        }
    }

    #pragma unroll
    for (int qi = 0; qi < 2; qi++) {
        int q0 = qi ? q0b : q0a;
        float l0 = lsum[qi][0], l1 = lsum[qi][1];
        l0 += __shfl_xor_sync(0xffffffffu, l0, 1);
        l0 += __shfl_xor_sync(0xffffffffu, l0, 2);
        l1 += __shfl_xor_sync(0xffffffffu, l1, 1);
        l1 += __shfl_xor_sync(0xffffffffu, l1, 2);
        float inv0 = 1.f / l0, inv1 = 1.f / l1;
        size_t r0 = bTok + q0 + g;
        size_t r1 = r0 + 8;
        bool wr1 = (q0 + g + 8) < S_;
        #pragma unroll
        for (int nt = 0; nt < 4; nt++) {
            int c = hoff + nt*8 + 2*t;
            float2 s0 = *(const float2*)&state[r0*64 + c];
            float2 o0;
            o0.x = fmaf(out[qi][nt][0], inv0, s0.x);
            o0.y = fmaf(out[qi][nt][1], inv0, s0.y);
            *(float2*)&g_z1[r0*64 + c] = o0;
            if (wr1) {
                float2 s1 = *(const float2*)&state[r1*64 + c];
                float2 o1;
                o1.x = fmaf(out[qi][nt][2], inv1, s1.x);
                o1.y = fmaf(out[qi][nt][3], inv1, s1.y);
                *(float2*)&g_z1[r1*64 + c] = o1;
            }
        }
    }
}

// ---------------- K3: LN -> FFN(gelu) -> +Z1 via mma (32 tok/block) ---------
// __launch_bounds__(256, 4): cap regs at 64 -> 4 resident blocks/SM
// (was 76 regs -> 3 blocks, occ 35%; kernel is occupancy-elastic per R14/R15).
#define ZR  72
#define H3R 264
#define Z1R 68
__global__ __launch_bounds__(256, 4)
void ffn_kernel(const float* __restrict__ b1, const float* __restrict__ b2,
                const float* __restrict__ g1, const float* __restrict__ beta1,
                float* __restrict__ out)
{
    __shared__ __align__(16) __half Z2s[32*ZR];
    __shared__ __align__(16) __half H3s[32*H3R];
    __shared__ __align__(16) float  Z1s[32*Z1R];
    const int tid = threadIdx.x;
    const size_t tok0 = (size_t)blockIdx.x * 32;

    {
        int tk = tid >> 3, sg = tid & 7;
        const float* src = g_z1 + (tok0 + tk)*64 + sg*8;
        float4 f0 = *(const float4*)src;
        float4 f1 = *(const float4*)(src + 4);
        float v[8] = {f0.x, f0.y, f0.z, f0.w, f1.x, f1.y, f1.z, f1.w};
        float s1 = 0.f, s2 = 0.f;
        #pragma unroll
        for (int u = 0; u < 8; u++) { s1 += v[u]; s2 = fmaf(v[u], v[u], s2); }
        #pragma unroll
        for (int off = 1; off <= 4; off <<= 1) {
            s1 += __shfl_xor_sync(0xffffffffu, s1, off);
            s2 += __shfl_xor_sync(0xffffffffu, s2, off);
        }
        float m = s1 * (1.f/64.f);
        float r = rsqrtf(s2*(1.f/64.f) - m*m + 1e-5f);
        *(float4*)(Z1s + tk*Z1R + sg*8)     = f0;
        *(float4*)(Z1s + tk*Z1R + sg*8 + 4) = f1;
        #pragma unroll
        for (int u = 0; u < 8; u += 2) {
            int c = sg*8 + u;
            float a0 = (v[u]   - m)*r*g1[c]   + beta1[c];
            float a1 = (v[u+1] - m)*r*g1[c+1] + beta1[c+1];
            *(__half2*)(Z2s + tk*ZR + c) = __floats2half2_rn(a0, a1);
        }
    }
    __syncthreads();

    const int w = tid >> 5, l = tid & 31;
    const int g = l >> 2, t = l & 3;
    const int ldrow = (l & 15), ldcol = (l >> 4) * 8;
    const int mt = w & 1;

    {
        const int cq = w >> 1;
        float acc1[8][4];
        #pragma unroll
        for (int nt = 0; nt < 8; nt++)
            #pragma unroll
            for (int i = 0; i < 4; i++) acc1[nt][i] = 0.f;
        #pragma unroll
        for (int ksp = 0; ksp < 2; ksp++) {
            unsigned int a[8];
            ldsm4(a,     Z2s + (mt*16 + ldrow)*ZR + ksp*32 + ldcol);
            ldsm4(a + 4, Z2s + (mt*16 + ldrow)*ZR + ksp*32 + 16 + ldcol);
            #pragma unroll
            for (int nt = 0; nt < 8; nt++) {
                const uint4 bfrag = *(const uint4*)&g_W1f[(((cq*8 + nt)*32 + l)*4 + ksp*2)*2];
                mma_f16(acc1[nt], a,     bfrag.x, bfrag.y);
                mma_f16(acc1[nt], a + 4, bfrag.z, bfrag.w);
            }
        }
        #pragma unroll
        for (int nt = 0; nt < 8; nt++) {
            int c0 = cq*64 + nt*8 + 2*t;
            float bb0 = b1[c0], bb1 = b1[c0 + 1];
            float x0 = acc1[nt][0] + bb0, x1 = acc1[nt][1] + bb1;
            float x2 = acc1[nt][2] + bb0, x3 = acc1[nt][3] + bb1;
            x0 = 0.5f*x0*(1.f + erff(x0*0.70710678118654752f));
            x1 = 0.5f*x1*(1.f + erff(x1*0.70710678118654752f));
            x2 = 0.5f*x2*(1.f + erff(x2*0.70710678118654752f));
            x3 = 0.5f*x3*(1.f + erff(x3*0.70710678118654752f));
            *(__half2*)(H3s + (mt*16 + g)*H3R + c0)     = __floats2half2_rn(x0, x1);
            *(__half2*)(H3s + (mt*16 + g + 8)*H3R + c0) = __floats2half2_rn(x2, x3);
        }
    }
    __syncthreads();

    {
        const int np = w >> 1;
        float acc2[2][4];
        #pragma unroll
        for (int nt = 0; nt < 2; nt++)
            #pragma unroll
            for (int i = 0; i < 4; i++) acc2[nt][i] = 0.f;
        #pragma unroll
        for (int ksp = 0; ksp < 8; ksp++) {
            unsigned int a[8];
            ldsm4(a,     H3s + (mt*16 + ldrow)*H3R + ksp*32 + ldcol);
            ldsm4(a + 4, H3s + (mt*16 + ldrow)*H3R + ksp*32 + 16 + ldcol);
            #pragma unroll
            for (int nt = 0; nt < 2; nt++) {
                const uint4 bfrag = *(const uint4*)&g_W2f[(((np*2 + nt)*32 + l)*16 + ksp*2)*2];
                mma_f16(acc2[nt], a,     bfrag.x, bfrag.y);
                mma_f16(acc2[nt], a + 4, bfrag.z, bfrag.w);
            }
        }
        #pragma unroll
        for (int nt = 0; nt < 2; nt++) {
            int c0 = np*16 + nt*8 + 2*t;
            int r0 = mt*16 + g;
            float bb0 = b2[c0], bb1 = b2[c0 + 1];
            out[(tok0 + r0)*64 + c0]       = acc2[nt][0] + bb0 + Z1s[r0*Z1R + c0];
            out[(tok0 + r0)*64 + c0 + 1]   = acc2[nt][1] + bb1 + Z1s[r0*Z1R + c0 + 1];
            out[(tok0 + r0 + 8)*64 + c0]   = acc2[nt][2] + bb0 + Z1s[(r0+8)*Z1R + c0];
            out[(tok0 + r0 + 8)*64 + c0+1] = acc2[nt][3] + bb1 + Z1s[(r0+8)*Z1R + c0 + 1];
        }
    }
}

// ---------------- launcher --------------------------------------------------
extern "C" void kernel_launch(void* const* d_in, const int* in_sizes, int n_in,
                              void* d_out, int out_size)
{
    const float* state  = (const float*)d_in[0];
    const float* H      = (const float*)d_in[1];
    const float* Wq     = (const float*)d_in[2];
    const float* bq     = (const float*)d_in[3];
    const float* Wk     = (const float*)d_in[4];
    const float* bk     = (const float*)d_in[5];
    const float* Wv     = (const float*)d_in[6];
    const float* bv     = (const float*)d_in[7];
    const float* Wcq    = (const float*)d_in[8];
    const float* bcq    = (const float*)d_in[9];
    const float* Wck    = (const float*)d_in[10];
    const float* bck    = (const float*)d_in[11];
    const float* Wcv    = (const float*)d_in[12];
    const float* bcv    = (const float*)d_in[13];
    const float* gQE    = (const float*)d_in[14];
    const float* betaQE = (const float*)d_in[15];
    const float* gKE    = (const float*)d_in[16];
    const float* betaKE = (const float*)d_in[17];
    const float* gVE    = (const float*)d_in[18];
    const float* betaVE = (const float*)d_in[19];
    const float* gQH    = (const float*)d_in[20];
    const float* betaQH = (const float*)d_in[21];
    const float* gKH    = (const float*)d_in[22];
    const float* betaKH = (const float*)d_in[23];
    const float* gVH    = (const float*)d_in[24];
    const float* betaVH = (const float*)d_in[25];
    const float* W1     = (const float*)d_in[26];
    const float* b1     = (const float*)d_in[27];
    const float* W2     = (const float*)d_in[28];
    const float* b2     = (const float*)d_in[29];
    const float* g1     = (const float*)d_in[30];
    const float* beta1  = (const float*)d_in[31];
    float* out = (float*)d_out;

    pack_kernel<<<192, 256>>>(Wq, bq, Wk, bk, Wv, bv,
                              Wcq, bcq, Wck, bck, Wcv, bcv,
                              gQE, betaQE, gKE, betaKE, gVE, betaVE,
                              gQH, betaQH, gKH, betaKH, gVH, betaVH,
                              W1, W2);
    proj_kernel<<<NTOK/32, 256>>>(state, H);
    attn_kernel<<<B_*2, 320>>>(state);
    ffn_kernel<<<NTOK/32, 256>>>(b1, b2, g1, beta1, out);
}